// round 15
// baseline (speedup 1.0000x reference)
#include <cuda_runtime.h>
#include <math.h>

#define NSENS 9
#define NEDGE 72
#define NPAIR 36
#define HDIM  128
#define NLAY  4
#define NTHREADS 320
#define EPSF 1e-8f
#define EP 132
#define HP 132
#define DP 68

typedef unsigned long long ull;

// 29 pre-transposed [col][k] weight matrices, 16384 floats each:
// 0: enc_e_w2 | 1+l: w1segC | 5+l: w2 | 9+l: w1segA | 13+l: w1segB
// 17+l: nw1segA(h_n) | 21+l: nw1segB(agg) | 25+l: nw2
__device__ float g_WT[29 * 16384 + 16];

struct SM {
    float h_n[NSENS * HP];
    float agg[NSENS * HP];
    float Pm [NSENS * HP];
    float Qm [NSENS * HP];
    float nhid[NSENS * HP];
    float h_e[NEDGE * EP];
    float hid[NEDGE * EP];
    float phys[NEDGE][8];
    float xs[NSENS][2];
    float dmg[2];
    float invdeg[NSENS];
    float dec[NEDGE];
    int   row_l[NEDGE];
    int   col_l[NEDGE];
    int   senders[NSENS][8];
    int   scnt[NSENS];
};

__device__ __forceinline__ ull pack2(float x) {
    ull r; asm("mov.b64 %0, {%1, %1};" : "=l"(r) : "f"(x)); return r;
}
__device__ __forceinline__ void ffma2(ull& d, ull a, ull b) {
    asm("fma.rn.f32x2 %0, %1, %2, %0;" : "+l"(d) : "l"(a), "l"(b));
}
__device__ __forceinline__ float2 unpack2(ull v) {
    float lo, hi; asm("mov.b64 {%0, %1}, %2;" : "=f"(lo), "=f"(hi) : "l"(v));
    return make_float2(lo, hi);
}

#define ZERO92(A) do {                                                      \
    _Pragma("unroll") for (int _j = 0; _j < 9; ++_j)                        \
    { (A)[_j][0] = 0ull; (A)[_j][1] = 0ull; }                               \
} while (0)

// ---------------------------------------------------------------------------
// 9-row x 2-col k-paired accumulation. Arow0 = ptr to row 0 of the 9 rows.
// Per 4k: 2 LDG.128 (W^T, prefetched) + 9 LDS.128 (A) + 36 FFMA2, no movs.
// ---------------------------------------------------------------------------
template<int AST>
__device__ __forceinline__ void kpass9(
    const float* __restrict__ WT, const float* __restrict__ Arow0,
    int co, ull (&acc)[9][2])
{
    const float* w0p = WT + co * HDIM;
    const float* w1p = w0p + HDIM;
    ulonglong2 wv0 = *(const ulonglong2*)(w0p);
    ulonglong2 wv1 = *(const ulonglong2*)(w1p);
#pragma unroll 1
    for (int kb = 0; kb < HDIM; kb += 4) {
        ulonglong2 nv0 = *(const ulonglong2*)(w0p + kb + 4);  // pad-safe overread
        ulonglong2 nv1 = *(const ulonglong2*)(w1p + kb + 4);
#pragma unroll
        for (int j = 0; j < 9; ++j) {
            ulonglong2 av = *(const ulonglong2*)(Arow0 + j * AST + kb);
            ffma2(acc[j][0], av.x, wv0.x);
            ffma2(acc[j][0], av.y, wv0.y);
            ffma2(acc[j][1], av.x, wv1.x);
            ffma2(acc[j][1], av.y, wv1.y);
        }
        wv0 = nv0; wv1 = nv1;
    }
}

// MODE: 0 = raw store, 1 = residual+bias, 2 = bias only
template<int MODE, int OST>
__device__ __forceinline__ void kepi9(
    ull (&acc)[9][2], const float* __restrict__ bias,
    float* __restrict__ Orow0, int co)
{
    float2 b = make_float2(0.f, 0.f);
    if (MODE != 0) b = *(const float2*)(bias + co);
#pragma unroll
    for (int j = 0; j < 9; ++j) {
        float2 p0 = unpack2(acc[j][0]);
        float2 p1 = unpack2(acc[j][1]);
        float s0 = p0.x + p0.y, s1 = p1.x + p1.y;
        float* o = Orow0 + j * OST + co;
        if (MODE == 0) {
            *(float2*)o = make_float2(s0, s1);
        } else if (MODE == 1) {
            float2 old = *(const float2*)o;
            *(float2*)o = make_float2(old.x + s0 + b.x, old.y + s1 + b.y);
        } else {
            *(float2*)o = make_float2(s0 + b.x, s1 + b.y);
        }
    }
}

// ---------------------------------------------------------------------------
// Prep: transpose all 128-col weight matrices into g_WT[(m*128+c)*128+k]
// ---------------------------------------------------------------------------
__global__ void prep_wt_kernel(const float* __restrict__ enc_e_w2,
                               const float* __restrict__ edge_w1,
                               const float* __restrict__ edge_w2,
                               const float* __restrict__ node_w1,
                               const float* __restrict__ node_w2)
{
    int i = blockIdx.x * blockDim.x + threadIdx.x;
    if (i >= 29 * 16384) return;
    int m = i >> 14;
    int r = i & 16383;
    int c = r >> 7;
    int k = r & 127;
    float v;
    if (m == 0)       v = enc_e_w2[k * HDIM + c];
    else if (m <= 4)  v = edge_w1[(m - 1)  * 3 * HDIM * HDIM + (2 * HDIM + k) * HDIM + c];
    else if (m <= 8)  v = edge_w2[(m - 5)  * HDIM * HDIM + k * HDIM + c];
    else if (m <= 12) v = edge_w1[(m - 9)  * 3 * HDIM * HDIM + k * HDIM + c];
    else if (m <= 16) v = edge_w1[(m - 13) * 3 * HDIM * HDIM + (HDIM + k) * HDIM + c];
    else if (m <= 20) v = node_w1[(m - 17) * 2 * HDIM * HDIM + k * HDIM + c];
    else if (m <= 24) v = node_w1[(m - 21) * 2 * HDIM * HDIM + (HDIM + k) * HDIM + c];
    else              v = node_w2[(m - 25) * HDIM * HDIM + k * HDIM + c];
    g_WT[i] = v;
}

// ---------------------------------------------------------------------------
// Fused GNN: one CTA per graph, 320 threads (10 warps)
// ---------------------------------------------------------------------------
__global__ __launch_bounds__(NTHREADS, 2)
void DirectPathAttenuationGNN_kernel(
    const float* __restrict__ x_nodes, const float* __restrict__ damage,
    const float* __restrict__ enc_n_w, const float* __restrict__ enc_n_b,
    const float* __restrict__ enc_e_w1, const float* __restrict__ enc_e_b1,
    const float* __restrict__ enc_e_b2,
    const float* __restrict__ edge_b1, const float* __restrict__ edge_b2,
    const float* __restrict__ node_b1, const float* __restrict__ node_b2,
    const float* __restrict__ dec_w1, const float* __restrict__ dec_b1,
    const float* __restrict__ dec_w2, const float* __restrict__ dec_b2,
    const int* __restrict__ edge_index, int Etot,
    float* __restrict__ out)
{
    extern __shared__ unsigned char smem_raw[];
    SM& sm = *reinterpret_cast<SM*>(smem_raw);

    const int g    = blockIdx.x;
    const int tid  = threadIdx.x;
    const int wid  = tid >> 5;
    const int lane = tid & 31;

    // edge-warp (0-7) column tiling: warp = 72 rows x 16 cols
    const int rbase  = (lane >> 2) * 9;
    const int cobase = wid * 16 + (lane & 3) * 2;
    // node-warp (8,9) column tiling: warp-half covers 64 cols, thread 9r x 2c
    const int co_n   = (wid - 8) * 64 + lane * 2;

    // ---- per-graph inputs -------------------------------------------------
    if (tid < NEDGE) {
        int ge = g * NEDGE + tid;
        sm.row_l[tid] = edge_index[ge]        - g * NSENS;
        sm.col_l[tid] = edge_index[Etot + ge] - g * NSENS;
    }
    if (tid < NSENS * 2) ((float*)sm.xs)[tid] = x_nodes[g * NSENS * 2 + tid];
    if (tid < 2)         sm.dmg[tid] = damage[g * 2 + tid];
    __syncthreads();

    if (tid < NSENS) {
        int cnt = 0;
        for (int e = 0; e < NEDGE; ++e)
            if (sm.col_l[e] == tid) { if (cnt < 8) sm.senders[tid][cnt] = sm.row_l[e]; ++cnt; }
        sm.scnt[tid]   = cnt < 8 ? cnt : 8;
        sm.invdeg[tid] = 1.0f / fmaxf((float)cnt, 1.0f);
    }

    if (tid < NEDGE) {
        int r = sm.row_l[tid], c = sm.col_l[tid];
        float sx = sm.xs[r][0], sy = sm.xs[r][1];
        float dx = sm.xs[c][0], dy = sm.xs[c][1];
        float g0 = sm.dmg[0],   g1 = sm.dmg[1];
        float vx = sx - dx, vy = sy - dy;
        float elen = sqrtf(vx * vx + vy * vy + EPSF);
        float d21x = -vx, d21y = -vy;
        float l2 = fmaxf(d21x * d21x + d21y * d21y, EPSF);
        float mx = g0 - sx, my = g1 - sy;
        float t = fminf(fmaxf((mx * d21x + my * d21y) / l2, 0.f), 1.f);
        float px = sx + t * d21x, py = sy + t * d21y;
        float qx = g0 - px, qy = g1 - py;
        float d_path = sqrtf(qx * qx + qy * qy + EPSF);
        float d_tx = sqrtf(mx * mx + my * my + EPSF);
        float rx = dx - g0, ry = dy - g1;
        float d_rx = sqrtf(rx * rx + ry * ry + EPSF);
        sm.phys[tid][0] = vx;   sm.phys[tid][1] = vy;
        sm.phys[tid][2] = elen; sm.phys[tid][3] = d_path;
        sm.phys[tid][4] = d_tx; sm.phys[tid][5] = d_rx;
    }

    // ---- node encoder (K=2) ----------------------------------------------
    if (tid < NSENS * 32) {
        int n = tid >> 5, c4 = lane;
        float x0 = sm.xs[n][0], x1 = sm.xs[n][1];
        float4 w0 = *(const float4*)(enc_n_w + (c4 << 2));
        float4 w1 = *(const float4*)(enc_n_w + HDIM + (c4 << 2));
        float4 b  = *(const float4*)(enc_n_b + (c4 << 2));
        *(float4*)&sm.h_n[n * HP + (c4 << 2)] =
            make_float4(fmaf(x1, w1.x, fmaf(x0, w0.x, b.x)),
                        fmaf(x1, w1.y, fmaf(x0, w0.y, b.y)),
                        fmaf(x1, w1.z, fmaf(x0, w0.z, b.z)),
                        fmaf(x1, w1.w, fmaf(x0, w0.w, b.w)));
    }
    __syncthreads();

    // ---- edge encoder hidden (K=6) -> hid ---------------------------------
    for (int idx = tid; idx < NEDGE * 32; idx += NTHREADS) {
        int e = idx >> 5, c4 = idx & 31;
        float4 a = *(const float4*)(enc_e_b1 + (c4 << 2));
#pragma unroll
        for (int k = 0; k < 6; ++k) {
            float p = sm.phys[e][k];
            float4 wv = *(const float4*)(enc_e_w1 + k * HDIM + (c4 << 2));
            a.x = fmaf(p, wv.x, a.x); a.y = fmaf(p, wv.y, a.y);
            a.z = fmaf(p, wv.z, a.z); a.w = fmaf(p, wv.w, a.w);
        }
        *(float4*)&sm.hid[e * EP + (c4 << 2)] =
            make_float4(fmaxf(a.x, 0.f), fmaxf(a.y, 0.f), fmaxf(a.z, 0.f), fmaxf(a.w, 0.f));
    }
    __syncthreads();

    // ---- edge encoder out -------------------------------------------------
    if (wid < 8) {
#pragma unroll 1
        for (int p = 0; p < 2; ++p) {
            ull acc[9][2]; ZERO92(acc);
            int co = cobase + p * 8;
            kpass9<EP>(g_WT, sm.hid + rbase * EP, co, acc);
            kepi9<2, EP>(acc, enc_e_b2, sm.h_e + rbase * EP, co);
        }
    }
    __syncthreads();

    // ---- 4 message-passing layers -----------------------------------------
    for (int l = 0; l < NLAY; ++l) {
        const float* wt1c = g_WT + (1 + l)  * 16384;
        const float* wt2  = g_WT + (5 + l)  * 16384;
        const float* wt1a = g_WT + (9 + l)  * 16384;
        const float* wt1b = g_WT + (13 + l) * 16384;
        const float* wn1a = g_WT + (17 + l) * 16384;
        const float* wn1b = g_WT + (21 + l) * 16384;
        const float* wn2  = g_WT + (25 + l) * 16384;
        const float* b1   = edge_b1 + l * HDIM;
        const float* b2   = edge_b2 + l * HDIM;
        const float* nb1  = node_b1 + l * HDIM;
        const float* nb2  = node_b2 + l * HDIM;

        // ===== phase A =====
        if (wid < 8) {
            // hid_raw = h_e @ W1c
#pragma unroll 1
            for (int p = 0; p < 2; ++p) {
                ull acc[9][2]; ZERO92(acc);
                int co = cobase + p * 8;
                kpass9<EP>(wt1c, sm.h_e + rbase * EP, co, acc);
                kepi9<0, EP>(acc, nullptr, sm.hid + rbase * EP, co);
            }
        } else {
            // agg halves: warp8 nodes 0-4, warp9 nodes 5-8
            int n0 = (wid == 8) ? 0 : 5, n1 = (wid == 8) ? 5 : 9;
            for (int n = n0; n < n1; ++n) {
                float4 s = make_float4(0.f, 0.f, 0.f, 0.f);
                int c = sm.scnt[n];
                for (int i = 0; i < c; ++i) {
                    float4 v = *(const float4*)&sm.h_n[sm.senders[n][i] * HP + (lane << 2)];
                    s.x += v.x; s.y += v.y; s.z += v.z; s.w += v.w;
                }
                float iv = sm.invdeg[n];
                *(float4*)&sm.agg[n * HP + (lane << 2)] =
                    make_float4(s.x * iv, s.y * iv, s.z * iv, s.w * iv);
            }
            // P = h_n @ W1a, Q = h_n @ W1b (each warp its 64-col half)
            {
                ull acc[9][2]; ZERO92(acc);
                kpass9<HP>(wt1a, sm.h_n, co_n, acc);
                kepi9<0, HP>(acc, nullptr, sm.Pm, co_n);
            }
            {
                ull acc[9][2]; ZERO92(acc);
                kpass9<HP>(wt1b, sm.h_n, co_n, acc);
                kepi9<0, HP>(acc, nullptr, sm.Qm, co_n);
            }
        }
        __syncthreads();

        // ===== phase MID =====
        if (wid < 8) {
            // node hidden, K split across lane pairs: col = wid*16 + (lane>>1),
            // lane&1 selects k-half of both K=128 segments; shfl-combine.
            int c  = wid * 16 + (lane >> 1);
            int kh = (lane & 1) * 64;
            const float* wA = wn1a + c * HDIM + kh;
            const float* wB = wn1b + c * HDIM + kh;
            ull a[9];
#pragma unroll
            for (int j = 0; j < 9; ++j) a[j] = 0ull;
#pragma unroll 1
            for (int kb = 0; kb < 64; kb += 4) {
                ulonglong2 w = *(const ulonglong2*)(wA + kb);
#pragma unroll
                for (int j = 0; j < 9; ++j) {
                    ulonglong2 av = *(const ulonglong2*)(&sm.h_n[j * HP + kh + kb]);
                    ffma2(a[j], av.x, w.x);
                    ffma2(a[j], av.y, w.y);
                }
            }
#pragma unroll 1
            for (int kb = 0; kb < 64; kb += 4) {
                ulonglong2 w = *(const ulonglong2*)(wB + kb);
#pragma unroll
                for (int j = 0; j < 9; ++j) {
                    ulonglong2 av = *(const ulonglong2*)(&sm.agg[j * HP + kh + kb]);
                    ffma2(a[j], av.x, w.x);
                    ffma2(a[j], av.y, w.y);
                }
            }
            float bc = nb1[c];
#pragma unroll
            for (int j = 0; j < 9; ++j) {
                float2 p = unpack2(a[j]);
                float s = p.x + p.y;
                s += __shfl_xor_sync(0xFFFFFFFF, s, 1);
                if ((lane & 1) == 0)
                    sm.nhid[j * HP + c] = fmaxf(s + bc, 0.f);
            }
        } else {
            // B1: hid = relu(hid + P[row] + Q[col] + b1), 64 lanes cover all
            for (int idx = (wid - 8) * 32 + lane; idx < NEDGE * 32; idx += 64) {
                int e = idx >> 5, coff = (idx & 31) << 2;
                float4 r = *(const float4*)&sm.hid[e * EP + coff];
                float4 P = *(const float4*)&sm.Pm[sm.row_l[e] * HP + coff];
                float4 Q = *(const float4*)&sm.Qm[sm.col_l[e] * HP + coff];
                float4 b = *(const float4*)(b1 + coff);
                *(float4*)&sm.hid[e * EP + coff] = make_float4(
                    fmaxf(r.x + P.x + Q.x + b.x, 0.f),
                    fmaxf(r.y + P.y + Q.y + b.y, 0.f),
                    fmaxf(r.z + P.z + Q.z + b.z, 0.f),
                    fmaxf(r.w + P.w + Q.w + b.w, 0.f));
            }
        }
        __syncthreads();

        // ===== phase END =====
        if (wid < 8) {
            // h_e += hid @ W2 + b2
#pragma unroll 1
            for (int p = 0; p < 2; ++p) {
                ull acc[9][2]; ZERO92(acc);
                int co = cobase + p * 8;
                kpass9<EP>(wt2, sm.hid + rbase * EP, co, acc);
                kepi9<1, EP>(acc, b2, sm.h_e + rbase * EP, co);
            }
        } else {
            // h_n += nhid @ nw2 + nb2 (each warp its 64-col half)
            ull acc[9][2]; ZERO92(acc);
            kpass9<HP>(wn2, sm.nhid, co_n, acc);
            kepi9<1, HP>(acc, nb2, sm.h_n, co_n);
        }
        __syncthreads();
    }

    // ---- decoder hidden ---------------------------------------------------
    float* dhid = sm.hid;
    for (int idx = tid; idx < NEDGE * 16; idx += NTHREADS) {
        int e = idx >> 4, c4 = idx & 15;
        const float* w = dec_w1 + (c4 << 2);
        ull a0 = 0ull, a1 = 0ull;
#pragma unroll 4
        for (int k = 0; k < HDIM; ++k) {
            ull s = pack2(sm.h_e[e * EP + k]);
            ulonglong2 wv = *(const ulonglong2*)(w + k * 64);
            ffma2(a0, s, wv.x); ffma2(a1, s, wv.y);
        }
        float4 b = *(const float4*)(dec_b1 + (c4 << 2));
        float2 p0 = unpack2(a0), p1 = unpack2(a1);
        *(float4*)&dhid[e * DP + (c4 << 2)] =
            make_float4(fmaxf(p0.x + b.x, 0.f), fmaxf(p0.y + b.y, 0.f),
                        fmaxf(p1.x + b.z, 0.f), fmaxf(p1.y + b.w, 0.f));
    }
    __syncthreads();

    if (tid < NEDGE) {
        float a = dec_b2[0];
#pragma unroll 4
        for (int k = 0; k < 64; ++k) a = fmaf(dhid[tid * DP + k], dec_w2[k], a);
        sm.dec[tid] = 1.f / (1.f + expf(-a));
    }
    __syncthreads();
    if (tid < NPAIR)
        out[g * NPAIR + tid] = 0.5f * (sm.dec[2 * tid] + sm.dec[2 * tid + 1]);
}

// ---------------------------------------------------------------------------
extern "C" void kernel_launch(void* const* d_in, const int* in_sizes, int n_in,
                              void* d_out, int out_size)
{
    const float* x_nodes   = (const float*)d_in[0];
    const float* damage    = (const float*)d_in[1];
    const float* enc_n_w   = (const float*)d_in[2];
    const float* enc_n_b   = (const float*)d_in[3];
    const float* enc_e_w1  = (const float*)d_in[4];
    const float* enc_e_b1  = (const float*)d_in[5];
    const float* enc_e_w2  = (const float*)d_in[6];
    const float* enc_e_b2  = (const float*)d_in[7];
    const float* edge_w1   = (const float*)d_in[8];
    const float* edge_b1   = (const float*)d_in[9];
    const float* edge_w2   = (const float*)d_in[10];
    const float* edge_b2   = (const float*)d_in[11];
    const float* node_w1   = (const float*)d_in[12];
    const float* node_b1   = (const float*)d_in[13];
    const float* node_w2   = (const float*)d_in[14];
    const float* node_b2   = (const float*)d_in[15];
    const float* dec_w1    = (const float*)d_in[16];
    const float* dec_b1    = (const float*)d_in[17];
    const float* dec_w2    = (const float*)d_in[18];
    const float* dec_b2    = (const float*)d_in[19];
    const int*   edge_idx  = (const int*)d_in[20];

    int Etot = in_sizes[20] / 2;
    int Bg   = Etot / NEDGE;

    prep_wt_kernel<<<(29 * 16384 + 255) / 256, 256>>>(enc_e_w2, edge_w1, edge_w2,
                                                      node_w1, node_w2);

    cudaFuncSetAttribute(DirectPathAttenuationGNN_kernel,
                         cudaFuncAttributeMaxDynamicSharedMemorySize,
                         (int)sizeof(SM));

    DirectPathAttenuationGNN_kernel<<<Bg, NTHREADS, sizeof(SM)>>>(
        x_nodes, damage,
        enc_n_w, enc_n_b, enc_e_w1, enc_e_b1, enc_e_b2,
        edge_b1, edge_b2, node_b1, node_b2,
        dec_w1, dec_b1, dec_w2, dec_b2,
        edge_idx, Etot,
        (float*)d_out);
}

// round 16
// speedup vs baseline: 1.0019x; 1.0019x over previous
#include <cuda_runtime.h>
#include <math.h>

#define NSENS 9
#define NEDGE 72
#define NPAIR 36
#define HDIM  128
#define NLAY  4
#define NTHREADS 320
#define EPSF 1e-8f
#define EP 132
#define HP 132
#define DP 68

typedef unsigned long long ull;

// 29 pre-transposed [col][k] weight matrices, 16384 floats each:
// 0: enc_e_w2 | 1+l: w1segC | 5+l: w2 | 9+l: w1segA | 13+l: w1segB
// 17+l: nw1segA(h_n) | 21+l: nw1segB(agg) | 25+l: nw2
__device__ float g_WT[29 * 16384 + 16];

struct SM {
    float h_n[NSENS * HP];
    float agg[NSENS * HP];
    float Pm [NSENS * HP];
    float Qm [NSENS * HP];
    float nhid[NSENS * HP];
    float h_e[NEDGE * EP];
    float hid[NEDGE * EP];
    float phys[NEDGE][8];
    float xs[NSENS][2];
    float dmg[2];
    float invdeg[NSENS];
    float dec[NEDGE];
    int   row_l[NEDGE];
    int   col_l[NEDGE];
    int   senders[NSENS][8];
    int   scnt[NSENS];
};

__device__ __forceinline__ ull pack2(float x) {
    ull r; asm("mov.b64 %0, {%1, %1};" : "=l"(r) : "f"(x)); return r;
}
__device__ __forceinline__ void ffma2(ull& d, ull a, ull b) {
    asm("fma.rn.f32x2 %0, %1, %2, %0;" : "+l"(d) : "l"(a), "l"(b));
}
__device__ __forceinline__ float2 unpack2(ull v) {
    float lo, hi; asm("mov.b64 {%0, %1}, %2;" : "=f"(lo), "=f"(hi) : "l"(v));
    return make_float2(lo, hi);
}

#define ZERO92(A) do {                                                      \
    _Pragma("unroll") for (int _j = 0; _j < 9; ++_j)                        \
    { (A)[_j][0] = 0ull; (A)[_j][1] = 0ull; }                               \
} while (0)

// ---------------------------------------------------------------------------
// 9-row x 2-col k-paired accumulation. Arow0 = ptr to row 0 of the 9 rows.
// Per 4k: 2 LDG.128 (W^T, prefetched) + 9 LDS.128 (A) + 36 FFMA2, no movs.
// ---------------------------------------------------------------------------
template<int AST>
__device__ __forceinline__ void kpass9(
    const float* __restrict__ WT, const float* __restrict__ Arow0,
    int co, ull (&acc)[9][2])
{
    const float* w0p = WT + co * HDIM;
    const float* w1p = w0p + HDIM;
    ulonglong2 wv0 = *(const ulonglong2*)(w0p);
    ulonglong2 wv1 = *(const ulonglong2*)(w1p);
#pragma unroll 1
    for (int kb = 0; kb < HDIM; kb += 4) {
        ulonglong2 nv0 = *(const ulonglong2*)(w0p + kb + 4);  // pad-safe overread
        ulonglong2 nv1 = *(const ulonglong2*)(w1p + kb + 4);
#pragma unroll
        for (int j = 0; j < 9; ++j) {
            ulonglong2 av = *(const ulonglong2*)(Arow0 + j * AST + kb);
            ffma2(acc[j][0], av.x, wv0.x);
            ffma2(acc[j][0], av.y, wv0.y);
            ffma2(acc[j][1], av.x, wv1.x);
            ffma2(acc[j][1], av.y, wv1.y);
        }
        wv0 = nv0; wv1 = nv1;
    }
}

// MODE: 0 = raw store, 1 = residual+bias, 2 = bias only
template<int MODE, int OST>
__device__ __forceinline__ void kepi9(
    ull (&acc)[9][2], const float* __restrict__ bias,
    float* __restrict__ Orow0, int co)
{
    float2 b = make_float2(0.f, 0.f);
    if (MODE != 0) b = *(const float2*)(bias + co);
#pragma unroll
    for (int j = 0; j < 9; ++j) {
        float2 p0 = unpack2(acc[j][0]);
        float2 p1 = unpack2(acc[j][1]);
        float s0 = p0.x + p0.y, s1 = p1.x + p1.y;
        float* o = Orow0 + j * OST + co;
        if (MODE == 0) {
            *(float2*)o = make_float2(s0, s1);
        } else if (MODE == 1) {
            float2 old = *(const float2*)o;
            *(float2*)o = make_float2(old.x + s0 + b.x, old.y + s1 + b.y);
        } else {
            *(float2*)o = make_float2(s0 + b.x, s1 + b.y);
        }
    }
}

// ---------------------------------------------------------------------------
// Prep: transpose all 128-col weight matrices into g_WT[(m*128+c)*128+k]
// ---------------------------------------------------------------------------
__global__ void prep_wt_kernel(const float* __restrict__ enc_e_w2,
                               const float* __restrict__ edge_w1,
                               const float* __restrict__ edge_w2,
                               const float* __restrict__ node_w1,
                               const float* __restrict__ node_w2)
{
    int i = blockIdx.x * blockDim.x + threadIdx.x;
    if (i >= 29 * 16384) return;
    int m = i >> 14;
    int r = i & 16383;
    int c = r >> 7;
    int k = r & 127;
    float v;
    if (m == 0)       v = enc_e_w2[k * HDIM + c];
    else if (m <= 4)  v = edge_w1[(m - 1)  * 3 * HDIM * HDIM + (2 * HDIM + k) * HDIM + c];
    else if (m <= 8)  v = edge_w2[(m - 5)  * HDIM * HDIM + k * HDIM + c];
    else if (m <= 12) v = edge_w1[(m - 9)  * 3 * HDIM * HDIM + k * HDIM + c];
    else if (m <= 16) v = edge_w1[(m - 13) * 3 * HDIM * HDIM + (HDIM + k) * HDIM + c];
    else if (m <= 20) v = node_w1[(m - 17) * 2 * HDIM * HDIM + k * HDIM + c];
    else if (m <= 24) v = node_w1[(m - 21) * 2 * HDIM * HDIM + (HDIM + k) * HDIM + c];
    else              v = node_w2[(m - 25) * HDIM * HDIM + k * HDIM + c];
    g_WT[i] = v;
}

// ---------------------------------------------------------------------------
// Fused GNN: one CTA per graph, 320 threads (10 warps)
// ---------------------------------------------------------------------------
__global__ __launch_bounds__(NTHREADS, 2)
void DirectPathAttenuationGNN_kernel(
    const float* __restrict__ x_nodes, const float* __restrict__ damage,
    const float* __restrict__ enc_n_w, const float* __restrict__ enc_n_b,
    const float* __restrict__ enc_e_w1, const float* __restrict__ enc_e_b1,
    const float* __restrict__ enc_e_b2,
    const float* __restrict__ edge_b1, const float* __restrict__ edge_b2,
    const float* __restrict__ node_b1, const float* __restrict__ node_b2,
    const float* __restrict__ dec_w1, const float* __restrict__ dec_b1,
    const float* __restrict__ dec_w2, const float* __restrict__ dec_b2,
    const int* __restrict__ edge_index, int Etot,
    float* __restrict__ out)
{
    extern __shared__ unsigned char smem_raw[];
    SM& sm = *reinterpret_cast<SM*>(smem_raw);

    const int g    = blockIdx.x;
    const int tid  = threadIdx.x;
    const int wid  = tid >> 5;
    const int lane = tid & 31;

    // edge-warp (0-7) column tiling: warp = 72 rows x 16 cols
    const int rbase  = (lane >> 2) * 9;
    const int cobase = wid * 16 + (lane & 3) * 2;
    // node-warp (8,9) column tiling: warp-half covers 64 cols, thread 9r x 2c
    const int co_n   = (wid - 8) * 64 + lane * 2;

    // ---- per-graph inputs -------------------------------------------------
    if (tid < NEDGE) {
        int ge = g * NEDGE + tid;
        sm.row_l[tid] = edge_index[ge]        - g * NSENS;
        sm.col_l[tid] = edge_index[Etot + ge] - g * NSENS;
    }
    if (tid < NSENS * 2) ((float*)sm.xs)[tid] = x_nodes[g * NSENS * 2 + tid];
    if (tid < 2)         sm.dmg[tid] = damage[g * 2 + tid];
    __syncthreads();

    if (tid < NSENS) {
        int cnt = 0;
        for (int e = 0; e < NEDGE; ++e)
            if (sm.col_l[e] == tid) { if (cnt < 8) sm.senders[tid][cnt] = sm.row_l[e]; ++cnt; }
        sm.scnt[tid]   = cnt < 8 ? cnt : 8;
        sm.invdeg[tid] = 1.0f / fmaxf((float)cnt, 1.0f);
    }

    if (tid < NEDGE) {
        int r = sm.row_l[tid], c = sm.col_l[tid];
        float sx = sm.xs[r][0], sy = sm.xs[r][1];
        float dx = sm.xs[c][0], dy = sm.xs[c][1];
        float g0 = sm.dmg[0],   g1 = sm.dmg[1];
        float vx = sx - dx, vy = sy - dy;
        float elen = sqrtf(vx * vx + vy * vy + EPSF);
        float d21x = -vx, d21y = -vy;
        float l2 = fmaxf(d21x * d21x + d21y * d21y, EPSF);
        float mx = g0 - sx, my = g1 - sy;
        float t = fminf(fmaxf((mx * d21x + my * d21y) / l2, 0.f), 1.f);
        float px = sx + t * d21x, py = sy + t * d21y;
        float qx = g0 - px, qy = g1 - py;
        float d_path = sqrtf(qx * qx + qy * qy + EPSF);
        float d_tx = sqrtf(mx * mx + my * my + EPSF);
        float rx = dx - g0, ry = dy - g1;
        float d_rx = sqrtf(rx * rx + ry * ry + EPSF);
        sm.phys[tid][0] = vx;   sm.phys[tid][1] = vy;
        sm.phys[tid][2] = elen; sm.phys[tid][3] = d_path;
        sm.phys[tid][4] = d_tx; sm.phys[tid][5] = d_rx;
    }

    // ---- node encoder (K=2) ----------------------------------------------
    if (tid < NSENS * 32) {
        int n = tid >> 5, c4 = lane;
        float x0 = sm.xs[n][0], x1 = sm.xs[n][1];
        float4 w0 = *(const float4*)(enc_n_w + (c4 << 2));
        float4 w1 = *(const float4*)(enc_n_w + HDIM + (c4 << 2));
        float4 b  = *(const float4*)(enc_n_b + (c4 << 2));
        *(float4*)&sm.h_n[n * HP + (c4 << 2)] =
            make_float4(fmaf(x1, w1.x, fmaf(x0, w0.x, b.x)),
                        fmaf(x1, w1.y, fmaf(x0, w0.y, b.y)),
                        fmaf(x1, w1.z, fmaf(x0, w0.z, b.z)),
                        fmaf(x1, w1.w, fmaf(x0, w0.w, b.w)));
    }
    __syncthreads();

    // ---- edge encoder hidden (K=6) -> hid ---------------------------------
    for (int idx = tid; idx < NEDGE * 32; idx += NTHREADS) {
        int e = idx >> 5, c4 = idx & 31;
        float4 a = *(const float4*)(enc_e_b1 + (c4 << 2));
#pragma unroll
        for (int k = 0; k < 6; ++k) {
            float p = sm.phys[e][k];
            float4 wv = *(const float4*)(enc_e_w1 + k * HDIM + (c4 << 2));
            a.x = fmaf(p, wv.x, a.x); a.y = fmaf(p, wv.y, a.y);
            a.z = fmaf(p, wv.z, a.z); a.w = fmaf(p, wv.w, a.w);
        }
        *(float4*)&sm.hid[e * EP + (c4 << 2)] =
            make_float4(fmaxf(a.x, 0.f), fmaxf(a.y, 0.f), fmaxf(a.z, 0.f), fmaxf(a.w, 0.f));
    }
    __syncthreads();

    // ---- edge encoder out -------------------------------------------------
    if (wid < 8) {
#pragma unroll 1
        for (int p = 0; p < 2; ++p) {
            ull acc[9][2]; ZERO92(acc);
            int co = cobase + p * 8;
            kpass9<EP>(g_WT, sm.hid + rbase * EP, co, acc);
            kepi9<2, EP>(acc, enc_e_b2, sm.h_e + rbase * EP, co);
        }
    }
    __syncthreads();

    // ---- 4 message-passing layers -----------------------------------------
    for (int l = 0; l < NLAY; ++l) {
        const float* wt1c = g_WT + (1 + l)  * 16384;
        const float* wt2  = g_WT + (5 + l)  * 16384;
        const float* wt1a = g_WT + (9 + l)  * 16384;
        const float* wt1b = g_WT + (13 + l) * 16384;
        const float* wn1a = g_WT + (17 + l) * 16384;
        const float* wn1b = g_WT + (21 + l) * 16384;
        const float* wn2  = g_WT + (25 + l) * 16384;
        const float* b1   = edge_b1 + l * HDIM;
        const float* b2   = edge_b2 + l * HDIM;
        const float* nb1  = node_b1 + l * HDIM;
        const float* nb2  = node_b2 + l * HDIM;

        // ===== phase A =====
        if (wid < 8) {
            // hid_raw = h_e @ W1c
#pragma unroll 1
            for (int p = 0; p < 2; ++p) {
                ull acc[9][2]; ZERO92(acc);
                int co = cobase + p * 8;
                kpass9<EP>(wt1c, sm.h_e + rbase * EP, co, acc);
                kepi9<0, EP>(acc, nullptr, sm.hid + rbase * EP, co);
            }
        } else {
            // agg halves: warp8 nodes 0-4, warp9 nodes 5-8
            int n0 = (wid == 8) ? 0 : 5, n1 = (wid == 8) ? 5 : 9;
            for (int n = n0; n < n1; ++n) {
                float4 s = make_float4(0.f, 0.f, 0.f, 0.f);
                int c = sm.scnt[n];
                for (int i = 0; i < c; ++i) {
                    float4 v = *(const float4*)&sm.h_n[sm.senders[n][i] * HP + (lane << 2)];
                    s.x += v.x; s.y += v.y; s.z += v.z; s.w += v.w;
                }
                float iv = sm.invdeg[n];
                *(float4*)&sm.agg[n * HP + (lane << 2)] =
                    make_float4(s.x * iv, s.y * iv, s.z * iv, s.w * iv);
            }
            // P = h_n @ W1a, Q = h_n @ W1b (each warp its 64-col half)
            {
                ull acc[9][2]; ZERO92(acc);
                kpass9<HP>(wt1a, sm.h_n, co_n, acc);
                kepi9<0, HP>(acc, nullptr, sm.Pm, co_n);
            }
            {
                ull acc[9][2]; ZERO92(acc);
                kpass9<HP>(wt1b, sm.h_n, co_n, acc);
                kepi9<0, HP>(acc, nullptr, sm.Qm, co_n);
            }
        }
        __syncthreads();

        // ===== phase MID =====
        if (wid < 8) {
            // node hidden, K split across lane pairs: col = wid*16 + (lane>>1),
            // lane&1 selects k-half of both K=128 segments; shfl-combine.
            int c  = wid * 16 + (lane >> 1);
            int kh = (lane & 1) * 64;
            const float* wA = wn1a + c * HDIM + kh;
            const float* wB = wn1b + c * HDIM + kh;
            ull a[9];
#pragma unroll
            for (int j = 0; j < 9; ++j) a[j] = 0ull;
#pragma unroll 1
            for (int kb = 0; kb < 64; kb += 4) {
                ulonglong2 w = *(const ulonglong2*)(wA + kb);
#pragma unroll
                for (int j = 0; j < 9; ++j) {
                    ulonglong2 av = *(const ulonglong2*)(&sm.h_n[j * HP + kh + kb]);
                    ffma2(a[j], av.x, w.x);
                    ffma2(a[j], av.y, w.y);
                }
            }
#pragma unroll 1
            for (int kb = 0; kb < 64; kb += 4) {
                ulonglong2 w = *(const ulonglong2*)(wB + kb);
#pragma unroll
                for (int j = 0; j < 9; ++j) {
                    ulonglong2 av = *(const ulonglong2*)(&sm.agg[j * HP + kh + kb]);
                    ffma2(a[j], av.x, w.x);
                    ffma2(a[j], av.y, w.y);
                }
            }
            float bc = nb1[c];
#pragma unroll
            for (int j = 0; j < 9; ++j) {
                float2 p = unpack2(a[j]);
                float s = p.x + p.y;
                s += __shfl_xor_sync(0xFFFFFFFF, s, 1);
                if ((lane & 1) == 0)
                    sm.nhid[j * HP + c] = fmaxf(s + bc, 0.f);
            }
        } else {
            // B1: hid = relu(hid + P[row] + Q[col] + b1), 64 lanes cover all
            for (int idx = (wid - 8) * 32 + lane; idx < NEDGE * 32; idx += 64) {
                int e = idx >> 5, coff = (idx & 31) << 2;
                float4 r = *(const float4*)&sm.hid[e * EP + coff];
                float4 P = *(const float4*)&sm.Pm[sm.row_l[e] * HP + coff];
                float4 Q = *(const float4*)&sm.Qm[sm.col_l[e] * HP + coff];
                float4 b = *(const float4*)(b1 + coff);
                *(float4*)&sm.hid[e * EP + coff] = make_float4(
                    fmaxf(r.x + P.x + Q.x + b.x, 0.f),
                    fmaxf(r.y + P.y + Q.y + b.y, 0.f),
                    fmaxf(r.z + P.z + Q.z + b.z, 0.f),
                    fmaxf(r.w + P.w + Q.w + b.w, 0.f));
            }
        }
        __syncthreads();

        // ===== phase END =====
        if (wid < 8) {
            // h_e += hid @ W2 + b2
#pragma unroll 1
            for (int p = 0; p < 2; ++p) {
                ull acc[9][2]; ZERO92(acc);
                int co = cobase + p * 8;
                kpass9<EP>(wt2, sm.hid + rbase * EP, co, acc);
                kepi9<1, EP>(acc, b2, sm.h_e + rbase * EP, co);
            }
        } else {
            // h_n += nhid @ nw2 + nb2 (each warp its 64-col half)
            ull acc[9][2]; ZERO92(acc);
            kpass9<HP>(wn2, sm.nhid, co_n, acc);
            kepi9<1, HP>(acc, nb2, sm.h_n, co_n);
        }
        __syncthreads();
    }

    // ---- decoder hidden ---------------------------------------------------
    float* dhid = sm.hid;
    for (int idx = tid; idx < NEDGE * 16; idx += NTHREADS) {
        int e = idx >> 4, c4 = idx & 15;
        const float* w = dec_w1 + (c4 << 2);
        ull a0 = 0ull, a1 = 0ull;
#pragma unroll 4
        for (int k = 0; k < HDIM; ++k) {
            ull s = pack2(sm.h_e[e * EP + k]);
            ulonglong2 wv = *(const ulonglong2*)(w + k * 64);
            ffma2(a0, s, wv.x); ffma2(a1, s, wv.y);
        }
        float4 b = *(const float4*)(dec_b1 + (c4 << 2));
        float2 p0 = unpack2(a0), p1 = unpack2(a1);
        *(float4*)&dhid[e * DP + (c4 << 2)] =
            make_float4(fmaxf(p0.x + b.x, 0.f), fmaxf(p0.y + b.y, 0.f),
                        fmaxf(p1.x + b.z, 0.f), fmaxf(p1.y + b.w, 0.f));
    }
    __syncthreads();

    if (tid < NEDGE) {
        float a = dec_b2[0];
#pragma unroll 4
        for (int k = 0; k < 64; ++k) a = fmaf(dhid[tid * DP + k], dec_w2[k], a);
        sm.dec[tid] = 1.f / (1.f + expf(-a));
    }
    __syncthreads();
    if (tid < NPAIR)
        out[g * NPAIR + tid] = 0.5f * (sm.dec[2 * tid] + sm.dec[2 * tid + 1]);
}

// ---------------------------------------------------------------------------
extern "C" void kernel_launch(void* const* d_in, const int* in_sizes, int n_in,
                              void* d_out, int out_size)
{
    const float* x_nodes   = (const float*)d_in[0];
    const float* damage    = (const float*)d_in[1];
    const float* enc_n_w   = (const float*)d_in[2];
    const float* enc_n_b   = (const float*)d_in[3];
    const float* enc_e_w1  = (const float*)d_in[4];
    const float* enc_e_b1  = (const float*)d_in[5];
    const float* enc_e_w2  = (const float*)d_in[6];
    const float* enc_e_b2  = (const float*)d_in[7];
    const float* edge_w1   = (const float*)d_in[8];
    const float* edge_b1   = (const float*)d_in[9];
    const float* edge_w2   = (const float*)d_in[10];
    const float* edge_b2   = (const float*)d_in[11];
    const float* node_w1   = (const float*)d_in[12];
    const float* node_b1   = (const float*)d_in[13];
    const float* node_w2   = (const float*)d_in[14];
    const float* node_b2   = (const float*)d_in[15];
    const float* dec_w1    = (const float*)d_in[16];
    const float* dec_b1    = (const float*)d_in[17];
    const float* dec_w2    = (const float*)d_in[18];
    const float* dec_b2    = (const float*)d_in[19];
    const int*   edge_idx  = (const int*)d_in[20];

    int Etot = in_sizes[20] / 2;
    int Bg   = Etot / NEDGE;

    prep_wt_kernel<<<(29 * 16384 + 255) / 256, 256>>>(enc_e_w2, edge_w1, edge_w2,
                                                      node_w1, node_w2);

    cudaFuncSetAttribute(DirectPathAttenuationGNN_kernel,
                         cudaFuncAttributeMaxDynamicSharedMemorySize,
                         (int)sizeof(SM));

    DirectPathAttenuationGNN_kernel<<<Bg, NTHREADS, sizeof(SM)>>>(
        x_nodes, damage,
        enc_n_w, enc_n_b, enc_e_w1, enc_e_b1, enc_e_b2,
        edge_b1, edge_b2, node_b1, node_b2,
        dec_w1, dec_b1, dec_w2, dec_b2,
        edge_idx, Etot,
        (float*)d_out);
}

// round 17
// speedup vs baseline: 1.0027x; 1.0009x over previous
#include <cuda_runtime.h>
#include <math.h>

#define NSENS 9
#define NEDGE 72
#define NPAIR 36
#define HDIM  128
#define NLAY  4
#define NTHREADS 320
#define EPSF 1e-8f
#define EP 132
#define HP 132
#define DP 68

typedef unsigned long long ull;

// 29 pre-transposed [col][k] weight matrices, 16384 floats each:
// 0: enc_e_w2 | 1+l: w1segC | 5+l: w2 | 9+l: w1segA | 13+l: w1segB
// 17+l: nw1segA(h_n) | 21+l: nw1segB(agg) | 25+l: nw2
__device__ float g_WT[29 * 16384 + 16];

struct SM {
    float h_n[NSENS * HP];
    float agg[NSENS * HP];
    float Pm [NSENS * HP];
    float Qm [NSENS * HP];
    float nhid[NSENS * HP];
    float h_e[NEDGE * EP];
    float hid[NEDGE * EP];
    float phys[NEDGE][8];
    float xs[NSENS][2];
    float dmg[2];
    float invdeg[NSENS];
    float dec[NEDGE];
    int   row_l[NEDGE];
    int   col_l[NEDGE];
    int   senders[NSENS][8];
    int   scnt[NSENS];
};

__device__ __forceinline__ ull pack2(float x) {
    ull r; asm("mov.b64 %0, {%1, %1};" : "=l"(r) : "f"(x)); return r;
}
__device__ __forceinline__ void ffma2(ull& d, ull a, ull b) {
    asm("fma.rn.f32x2 %0, %1, %2, %0;" : "+l"(d) : "l"(a), "l"(b));
}
__device__ __forceinline__ float2 unpack2(ull v) {
    float lo, hi; asm("mov.b64 {%0, %1}, %2;" : "=f"(lo), "=f"(hi) : "l"(v));
    return make_float2(lo, hi);
}

#define ZERO92(A) do {                                                      \
    _Pragma("unroll") for (int _j = 0; _j < 9; ++_j)                        \
    { (A)[_j][0] = 0ull; (A)[_j][1] = 0ull; }                               \
} while (0)

// ---------------------------------------------------------------------------
// 9-row x 2-col k-paired accumulation. Arow0 = ptr to row 0 of the 9 rows.
// Per 4k: 2 LDG.128 (W^T, prefetched) + 9 LDS.128 (A) + 36 FFMA2, no movs.
// ---------------------------------------------------------------------------
template<int AST>
__device__ __forceinline__ void kpass9(
    const float* __restrict__ WT, const float* __restrict__ Arow0,
    int co, ull (&acc)[9][2])
{
    const float* w0p = WT + co * HDIM;
    const float* w1p = w0p + HDIM;
    ulonglong2 wv0 = *(const ulonglong2*)(w0p);
    ulonglong2 wv1 = *(const ulonglong2*)(w1p);
#pragma unroll 1
    for (int kb = 0; kb < HDIM; kb += 4) {
        ulonglong2 nv0 = *(const ulonglong2*)(w0p + kb + 4);  // pad-safe overread
        ulonglong2 nv1 = *(const ulonglong2*)(w1p + kb + 4);
#pragma unroll
        for (int j = 0; j < 9; ++j) {
            ulonglong2 av = *(const ulonglong2*)(Arow0 + j * AST + kb);
            ffma2(acc[j][0], av.x, wv0.x);
            ffma2(acc[j][0], av.y, wv0.y);
            ffma2(acc[j][1], av.x, wv1.x);
            ffma2(acc[j][1], av.y, wv1.y);
        }
        wv0 = nv0; wv1 = nv1;
    }
}

// MODE: 0 = raw store, 1 = residual+bias, 2 = bias only
template<int MODE, int OST>
__device__ __forceinline__ void kepi9(
    ull (&acc)[9][2], const float* __restrict__ bias,
    float* __restrict__ Orow0, int co)
{
    float2 b = make_float2(0.f, 0.f);
    if (MODE != 0) b = *(const float2*)(bias + co);
#pragma unroll
    for (int j = 0; j < 9; ++j) {
        float2 p0 = unpack2(acc[j][0]);
        float2 p1 = unpack2(acc[j][1]);
        float s0 = p0.x + p0.y, s1 = p1.x + p1.y;
        float* o = Orow0 + j * OST + co;
        if (MODE == 0) {
            *(float2*)o = make_float2(s0, s1);
        } else if (MODE == 1) {
            float2 old = *(const float2*)o;
            *(float2*)o = make_float2(old.x + s0 + b.x, old.y + s1 + b.y);
        } else {
            *(float2*)o = make_float2(s0 + b.x, s1 + b.y);
        }
    }
}

// ---------------------------------------------------------------------------
// Prep: transpose all 128-col weight matrices into g_WT[(m*128+c)*128+k]
// ---------------------------------------------------------------------------
__global__ void prep_wt_kernel(const float* __restrict__ enc_e_w2,
                               const float* __restrict__ edge_w1,
                               const float* __restrict__ edge_w2,
                               const float* __restrict__ node_w1,
                               const float* __restrict__ node_w2)
{
    int i = blockIdx.x * blockDim.x + threadIdx.x;
    if (i >= 29 * 16384) return;
    int m = i >> 14;
    int r = i & 16383;
    int c = r >> 7;
    int k = r & 127;
    float v;
    if (m == 0)       v = enc_e_w2[k * HDIM + c];
    else if (m <= 4)  v = edge_w1[(m - 1)  * 3 * HDIM * HDIM + (2 * HDIM + k) * HDIM + c];
    else if (m <= 8)  v = edge_w2[(m - 5)  * HDIM * HDIM + k * HDIM + c];
    else if (m <= 12) v = edge_w1[(m - 9)  * 3 * HDIM * HDIM + k * HDIM + c];
    else if (m <= 16) v = edge_w1[(m - 13) * 3 * HDIM * HDIM + (HDIM + k) * HDIM + c];
    else if (m <= 20) v = node_w1[(m - 17) * 2 * HDIM * HDIM + k * HDIM + c];
    else if (m <= 24) v = node_w1[(m - 21) * 2 * HDIM * HDIM + (HDIM + k) * HDIM + c];
    else              v = node_w2[(m - 25) * HDIM * HDIM + k * HDIM + c];
    g_WT[i] = v;
}

// ---------------------------------------------------------------------------
// Fused GNN: one CTA per graph, 320 threads (10 warps)
// ---------------------------------------------------------------------------
__global__ __launch_bounds__(NTHREADS, 2)
void DirectPathAttenuationGNN_kernel(
    const float* __restrict__ x_nodes, const float* __restrict__ damage,
    const float* __restrict__ enc_n_w, const float* __restrict__ enc_n_b,
    const float* __restrict__ enc_e_w1, const float* __restrict__ enc_e_b1,
    const float* __restrict__ enc_e_b2,
    const float* __restrict__ edge_b1, const float* __restrict__ edge_b2,
    const float* __restrict__ node_b1, const float* __restrict__ node_b2,
    const float* __restrict__ dec_w1, const float* __restrict__ dec_b1,
    const float* __restrict__ dec_w2, const float* __restrict__ dec_b2,
    const int* __restrict__ edge_index, int Etot,
    float* __restrict__ out)
{
    extern __shared__ unsigned char smem_raw[];
    SM& sm = *reinterpret_cast<SM*>(smem_raw);

    const int g    = blockIdx.x;
    const int tid  = threadIdx.x;
    const int wid  = tid >> 5;
    const int lane = tid & 31;

    // edge-warp (0-7) column tiling: warp = 72 rows x 16 cols
    const int rbase  = (lane >> 2) * 9;
    const int cobase = wid * 16 + (lane & 3) * 2;
    // node-warp (8,9) column tiling: warp-half covers 64 cols, thread 9r x 2c
    const int co_n   = (wid - 8) * 64 + lane * 2;

    // ---- per-graph inputs -------------------------------------------------
    if (tid < NEDGE) {
        int ge = g * NEDGE + tid;
        sm.row_l[tid] = edge_index[ge]        - g * NSENS;
        sm.col_l[tid] = edge_index[Etot + ge] - g * NSENS;
    }
    if (tid < NSENS * 2) ((float*)sm.xs)[tid] = x_nodes[g * NSENS * 2 + tid];
    if (tid < 2)         sm.dmg[tid] = damage[g * 2 + tid];
    __syncthreads();

    if (tid < NSENS) {
        int cnt = 0;
        for (int e = 0; e < NEDGE; ++e)
            if (sm.col_l[e] == tid) { if (cnt < 8) sm.senders[tid][cnt] = sm.row_l[e]; ++cnt; }
        sm.scnt[tid]   = cnt < 8 ? cnt : 8;
        sm.invdeg[tid] = 1.0f / fmaxf((float)cnt, 1.0f);
    }

    if (tid < NEDGE) {
        int r = sm.row_l[tid], c = sm.col_l[tid];
        float sx = sm.xs[r][0], sy = sm.xs[r][1];
        float dx = sm.xs[c][0], dy = sm.xs[c][1];
        float g0 = sm.dmg[0],   g1 = sm.dmg[1];
        float vx = sx - dx, vy = sy - dy;
        float elen = sqrtf(vx * vx + vy * vy + EPSF);
        float d21x = -vx, d21y = -vy;
        float l2 = fmaxf(d21x * d21x + d21y * d21y, EPSF);
        float mx = g0 - sx, my = g1 - sy;
        float t = fminf(fmaxf((mx * d21x + my * d21y) / l2, 0.f), 1.f);
        float px = sx + t * d21x, py = sy + t * d21y;
        float qx = g0 - px, qy = g1 - py;
        float d_path = sqrtf(qx * qx + qy * qy + EPSF);
        float d_tx = sqrtf(mx * mx + my * my + EPSF);
        float rx = dx - g0, ry = dy - g1;
        float d_rx = sqrtf(rx * rx + ry * ry + EPSF);
        sm.phys[tid][0] = vx;   sm.phys[tid][1] = vy;
        sm.phys[tid][2] = elen; sm.phys[tid][3] = d_path;
        sm.phys[tid][4] = d_tx; sm.phys[tid][5] = d_rx;
    }

    // ---- node encoder (K=2) ----------------------------------------------
    if (tid < NSENS * 32) {
        int n = tid >> 5, c4 = lane;
        float x0 = sm.xs[n][0], x1 = sm.xs[n][1];
        float4 w0 = *(const float4*)(enc_n_w + (c4 << 2));
        float4 w1 = *(const float4*)(enc_n_w + HDIM + (c4 << 2));
        float4 b  = *(const float4*)(enc_n_b + (c4 << 2));
        *(float4*)&sm.h_n[n * HP + (c4 << 2)] =
            make_float4(fmaf(x1, w1.x, fmaf(x0, w0.x, b.x)),
                        fmaf(x1, w1.y, fmaf(x0, w0.y, b.y)),
                        fmaf(x1, w1.z, fmaf(x0, w0.z, b.z)),
                        fmaf(x1, w1.w, fmaf(x0, w0.w, b.w)));
    }
    __syncthreads();

    // ---- edge encoder hidden (K=6) -> hid ---------------------------------
    for (int idx = tid; idx < NEDGE * 32; idx += NTHREADS) {
        int e = idx >> 5, c4 = idx & 31;
        float4 a = *(const float4*)(enc_e_b1 + (c4 << 2));
#pragma unroll
        for (int k = 0; k < 6; ++k) {
            float p = sm.phys[e][k];
            float4 wv = *(const float4*)(enc_e_w1 + k * HDIM + (c4 << 2));
            a.x = fmaf(p, wv.x, a.x); a.y = fmaf(p, wv.y, a.y);
            a.z = fmaf(p, wv.z, a.z); a.w = fmaf(p, wv.w, a.w);
        }
        *(float4*)&sm.hid[e * EP + (c4 << 2)] =
            make_float4(fmaxf(a.x, 0.f), fmaxf(a.y, 0.f), fmaxf(a.z, 0.f), fmaxf(a.w, 0.f));
    }
    __syncthreads();

    // ---- edge encoder out -------------------------------------------------
    if (wid < 8) {
#pragma unroll 1
        for (int p = 0; p < 2; ++p) {
            ull acc[9][2]; ZERO92(acc);
            int co = cobase + p * 8;
            kpass9<EP>(g_WT, sm.hid + rbase * EP, co, acc);
            kepi9<2, EP>(acc, enc_e_b2, sm.h_e + rbase * EP, co);
        }
    }
    __syncthreads();

    // ---- 4 message-passing layers -----------------------------------------
    for (int l = 0; l < NLAY; ++l) {
        const float* wt1c = g_WT + (1 + l)  * 16384;
        const float* wt2  = g_WT + (5 + l)  * 16384;
        const float* wt1a = g_WT + (9 + l)  * 16384;
        const float* wt1b = g_WT + (13 + l) * 16384;
        const float* wn1a = g_WT + (17 + l) * 16384;
        const float* wn1b = g_WT + (21 + l) * 16384;
        const float* wn2  = g_WT + (25 + l) * 16384;
        const float* b1   = edge_b1 + l * HDIM;
        const float* b2   = edge_b2 + l * HDIM;
        const float* nb1  = node_b1 + l * HDIM;
        const float* nb2  = node_b2 + l * HDIM;

        // ===== phase A =====
        if (wid < 8) {
            // hid_raw = h_e @ W1c
#pragma unroll 1
            for (int p = 0; p < 2; ++p) {
                ull acc[9][2]; ZERO92(acc);
                int co = cobase + p * 8;
                kpass9<EP>(wt1c, sm.h_e + rbase * EP, co, acc);
                kepi9<0, EP>(acc, nullptr, sm.hid + rbase * EP, co);
            }
        } else {
            // agg halves: warp8 nodes 0-4, warp9 nodes 5-8
            int n0 = (wid == 8) ? 0 : 5, n1 = (wid == 8) ? 5 : 9;
            for (int n = n0; n < n1; ++n) {
                float4 s = make_float4(0.f, 0.f, 0.f, 0.f);
                int c = sm.scnt[n];
                for (int i = 0; i < c; ++i) {
                    float4 v = *(const float4*)&sm.h_n[sm.senders[n][i] * HP + (lane << 2)];
                    s.x += v.x; s.y += v.y; s.z += v.z; s.w += v.w;
                }
                float iv = sm.invdeg[n];
                *(float4*)&sm.agg[n * HP + (lane << 2)] =
                    make_float4(s.x * iv, s.y * iv, s.z * iv, s.w * iv);
            }
            // P = h_n @ W1a, Q = h_n @ W1b (each warp its 64-col half)
            {
                ull acc[9][2]; ZERO92(acc);
                kpass9<HP>(wt1a, sm.h_n, co_n, acc);
                kepi9<0, HP>(acc, nullptr, sm.Pm, co_n);
            }
            {
                ull acc[9][2]; ZERO92(acc);
                kpass9<HP>(wt1b, sm.h_n, co_n, acc);
                kepi9<0, HP>(acc, nullptr, sm.Qm, co_n);
            }
        }
        __syncthreads();

        // ===== phase MID =====
        if (wid < 8) {
            // node hidden, K split across lane pairs: col = wid*16 + (lane>>1),
            // lane&1 selects k-half of both K=128 segments; shfl-combine.
            int c  = wid * 16 + (lane >> 1);
            int kh = (lane & 1) * 64;
            const float* wA = wn1a + c * HDIM + kh;
            const float* wB = wn1b + c * HDIM + kh;
            ull a[9];
#pragma unroll
            for (int j = 0; j < 9; ++j) a[j] = 0ull;
#pragma unroll 1
            for (int kb = 0; kb < 64; kb += 4) {
                ulonglong2 w = *(const ulonglong2*)(wA + kb);
#pragma unroll
                for (int j = 0; j < 9; ++j) {
                    ulonglong2 av = *(const ulonglong2*)(&sm.h_n[j * HP + kh + kb]);
                    ffma2(a[j], av.x, w.x);
                    ffma2(a[j], av.y, w.y);
                }
            }
#pragma unroll 1
            for (int kb = 0; kb < 64; kb += 4) {
                ulonglong2 w = *(const ulonglong2*)(wB + kb);
#pragma unroll
                for (int j = 0; j < 9; ++j) {
                    ulonglong2 av = *(const ulonglong2*)(&sm.agg[j * HP + kh + kb]);
                    ffma2(a[j], av.x, w.x);
                    ffma2(a[j], av.y, w.y);
                }
            }
            float bc = nb1[c];
#pragma unroll
            for (int j = 0; j < 9; ++j) {
                float2 p = unpack2(a[j]);
                float s = p.x + p.y;
                s += __shfl_xor_sync(0xFFFFFFFF, s, 1);
                if ((lane & 1) == 0)
                    sm.nhid[j * HP + c] = fmaxf(s + bc, 0.f);
            }
        } else {
            // B1: hid = relu(hid + P[row] + Q[col] + b1), 64 lanes cover all
            for (int idx = (wid - 8) * 32 + lane; idx < NEDGE * 32; idx += 64) {
                int e = idx >> 5, coff = (idx & 31) << 2;
                float4 r = *(const float4*)&sm.hid[e * EP + coff];
                float4 P = *(const float4*)&sm.Pm[sm.row_l[e] * HP + coff];
                float4 Q = *(const float4*)&sm.Qm[sm.col_l[e] * HP + coff];
                float4 b = *(const float4*)(b1 + coff);
                *(float4*)&sm.hid[e * EP + coff] = make_float4(
                    fmaxf(r.x + P.x + Q.x + b.x, 0.f),
                    fmaxf(r.y + P.y + Q.y + b.y, 0.f),
                    fmaxf(r.z + P.z + Q.z + b.z, 0.f),
                    fmaxf(r.w + P.w + Q.w + b.w, 0.f));
            }
        }
        __syncthreads();

        // ===== phase END =====
        if (wid < 8) {
            // h_e += hid @ W2 + b2
#pragma unroll 1
            for (int p = 0; p < 2; ++p) {
                ull acc[9][2]; ZERO92(acc);
                int co = cobase + p * 8;
                kpass9<EP>(wt2, sm.hid + rbase * EP, co, acc);
                kepi9<1, EP>(acc, b2, sm.h_e + rbase * EP, co);
            }
        } else {
            // h_n += nhid @ nw2 + nb2 (each warp its 64-col half)
            ull acc[9][2]; ZERO92(acc);
            kpass9<HP>(wn2, sm.nhid, co_n, acc);
            kepi9<1, HP>(acc, nb2, sm.h_n, co_n);
        }
        __syncthreads();
    }

    // ---- decoder hidden ---------------------------------------------------
    float* dhid = sm.hid;
    for (int idx = tid; idx < NEDGE * 16; idx += NTHREADS) {
        int e = idx >> 4, c4 = idx & 15;
        const float* w = dec_w1 + (c4 << 2);
        ull a0 = 0ull, a1 = 0ull;
#pragma unroll 4
        for (int k = 0; k < HDIM; ++k) {
            ull s = pack2(sm.h_e[e * EP + k]);
            ulonglong2 wv = *(const ulonglong2*)(w + k * 64);
            ffma2(a0, s, wv.x); ffma2(a1, s, wv.y);
        }
        float4 b = *(const float4*)(dec_b1 + (c4 << 2));
        float2 p0 = unpack2(a0), p1 = unpack2(a1);
        *(float4*)&dhid[e * DP + (c4 << 2)] =
            make_float4(fmaxf(p0.x + b.x, 0.f), fmaxf(p0.y + b.y, 0.f),
                        fmaxf(p1.x + b.z, 0.f), fmaxf(p1.y + b.w, 0.f));
    }
    __syncthreads();

    if (tid < NEDGE) {
        float a = dec_b2[0];
#pragma unroll 4
        for (int k = 0; k < 64; ++k) a = fmaf(dhid[tid * DP + k], dec_w2[k], a);
        sm.dec[tid] = 1.f / (1.f + expf(-a));
    }
    __syncthreads();
    if (tid < NPAIR)
        out[g * NPAIR + tid] = 0.5f * (sm.dec[2 * tid] + sm.dec[2 * tid + 1]);
}

// ---------------------------------------------------------------------------
extern "C" void kernel_launch(void* const* d_in, const int* in_sizes, int n_in,
                              void* d_out, int out_size)
{
    const float* x_nodes   = (const float*)d_in[0];
    const float* damage    = (const float*)d_in[1];
    const float* enc_n_w   = (const float*)d_in[2];
    const float* enc_n_b   = (const float*)d_in[3];
    const float* enc_e_w1  = (const float*)d_in[4];
    const float* enc_e_b1  = (const float*)d_in[5];
    const float* enc_e_w2  = (const float*)d_in[6];
    const float* enc_e_b2  = (const float*)d_in[7];
    const float* edge_w1   = (const float*)d_in[8];
    const float* edge_b1   = (const float*)d_in[9];
    const float* edge_w2   = (const float*)d_in[10];
    const float* edge_b2   = (const float*)d_in[11];
    const float* node_w1   = (const float*)d_in[12];
    const float* node_b1   = (const float*)d_in[13];
    const float* node_w2   = (const float*)d_in[14];
    const float* node_b2   = (const float*)d_in[15];
    const float* dec_w1    = (const float*)d_in[16];
    const float* dec_b1    = (const float*)d_in[17];
    const float* dec_w2    = (const float*)d_in[18];
    const float* dec_b2    = (const float*)d_in[19];
    const int*   edge_idx  = (const int*)d_in[20];

    int Etot = in_sizes[20] / 2;
    int Bg   = Etot / NEDGE;

    prep_wt_kernel<<<(29 * 16384 + 255) / 256, 256>>>(enc_e_w2, edge_w1, edge_w2,
                                                      node_w1, node_w2);

    cudaFuncSetAttribute(DirectPathAttenuationGNN_kernel,
                         cudaFuncAttributeMaxDynamicSharedMemorySize,
                         (int)sizeof(SM));

    DirectPathAttenuationGNN_kernel<<<Bg, NTHREADS, sizeof(SM)>>>(
        x_nodes, damage,
        enc_n_w, enc_n_b, enc_e_w1, enc_e_b1, enc_e_b2,
        edge_b1, edge_b2, node_b1, node_b2,
        dec_w1, dec_b1, dec_w2, dec_b2,
        edge_idx, Etot,
        (float*)d_out);
}